// round 12
// baseline (speedup 1.0000x reference)
#include <cuda_runtime.h>
#include <math.h>

// PDHG / Chambolle-Pock TV denoising, persistent kernel, SLAB decomposition +
// fused flag+payload message passing for the x-halo.
// P=2, C=1, NX=128, NY=128, NT=8; T=128 iterations.
// CTA = slab of 2 x-rows x full 128 y (256 threads, 1 pencil/thread).
// y-halo + partner-row: intra-CTA via double-buffered SMEM.
// x-halo: one 128B staging entry per boundary pencil holding BOTH payload
// buffers and the seq word -> the poll round returns the payload itself
// (no separate post-discovery load, no separate flag array, no g_xbar).

#define NXD 128
#define NYD 128
#define NTD 8
#define NPB 2
#define NSLAB 64
#define NCTA (NSLAB * NPB)              // 128
#define NTHR 256
#define ESTR 32                          // entry stride in floats (128 B)

// staging: [cta][row r][y] -> 32 floats: [0..7]=buf0, [8..15]=buf1, [16]=seq
__device__ __align__(128) float g_stage[NCTA * 2 * 128][ESTR];

// ---- memory-model primitives ----
__device__ __forceinline__ void st_release_gpu_u32(unsigned* p, unsigned v) {
    asm volatile("st.release.gpu.global.u32 [%0], %1;" :: "l"(p), "r"(v) : "memory");
}
__device__ __forceinline__ unsigned ld_acquire_gpu(const unsigned* p) {
    unsigned v;
    asm volatile("ld.acquire.gpu.global.u32 %0, [%1];" : "=r"(v) : "l"(p) : "memory");
    return v;
}
__device__ __forceinline__ void stcg_v4(float* p, float a, float b, float c, float d) {
    asm volatile("st.global.cg.v4.f32 [%0], {%1,%2,%3,%4};"
                 :: "l"(p), "f"(a), "f"(b), "f"(c), "f"(d) : "memory");
}
__device__ __forceinline__ float4 ldcg_v4(const float* p) {
    float4 v;
    asm volatile("ld.global.cg.v4.f32 {%0,%1,%2,%3}, [%4];"
                 : "=f"(v.x), "=f"(v.y), "=f"(v.z), "=f"(v.w) : "l"(p) : "memory");
    return v;
}

#define LOADP(dst, ptr, off) do { \
    float4 a_ = *reinterpret_cast<const float4*>((ptr) + (off)); \
    float4 b_ = *reinterpret_cast<const float4*>((ptr) + (off) + 4); \
    dst[0]=a_.x; dst[1]=a_.y; dst[2]=a_.z; dst[3]=a_.w; \
    dst[4]=b_.x; dst[5]=b_.y; dst[6]=b_.z; dst[7]=b_.w; } while(0)

#define STOREP(ptr, off, src) do { \
    *reinterpret_cast<float4*>((ptr) + (off))     = make_float4(src[0],src[1],src[2],src[3]); \
    *reinterpret_cast<float4*>((ptr) + (off) + 4) = make_float4(src[4],src[5],src[6],src[7]); } while(0)

#define LOADS(dst, smemrow) do { \
    float4 a_ = *reinterpret_cast<const float4*>(smemrow); \
    float4 b_ = *reinterpret_cast<const float4*>((smemrow) + 4); \
    dst[0]=a_.x; dst[1]=a_.y; dst[2]=a_.z; dst[3]=a_.w; \
    dst[4]=b_.x; dst[5]=b_.y; dst[6]=b_.z; dst[7]=b_.w; } while(0)

extern "C" __global__ void __launch_bounds__(NTHR, 1)
pdhg_persist_kernel(const float* __restrict__ xin,
                    const float* __restrict__ lamin,
                    const float* __restrict__ taup,
                    const float* __restrict__ sigp,
                    const float* __restrict__ thp,
                    const int*   __restrict__ Tp,
                    float* __restrict__ out)
{
    __shared__ float sm_xb[2][NTHR][NTD];   // 16 KB, double-buffered xbar

    // ---- scalars ----
    const float L    = sqrtf(13.0f);
    const float sig  = (1.0f / (1.0f + expf(-sigp[0]))) / L;
    const float tauv = (1.0f / (1.0f + expf(-taup[0]))) / L;
    const float th   = 1.0f / (1.0f + expf(-thp[0]));
    const float i1s  = 1.0f / (1.0f + sig);

    int T = Tp[0];
    if (T < 1 || T > 65536) {
        float tf = __int_as_float(T);
        T = (int)tf;
        if (T < 1 || T > 65536) T = 128;
    }

    // ---- mapping ----
    const int cta = blockIdx.x;           // 0..127
    const int pp  = cta >> 6;             // batch
    const int s   = cta & 63;             // slab (rows 2s, 2s+1)
    const int tid = threadIdx.x;
    const int r   = tid >> 7;             // 0 or 1
    const int y   = tid & 127;
    const int x   = (s << 1) + r;
    const int yp  = (y + 1) & 127, ym = (y - 1) & 127;

    const int pb = pp << 14;
    const int o  = (pb + (x << 7) + y) << 3;           // own pencil in xin/out
    const int omx = (pb + (((x - 1) & 127) << 7) + y) << 3;
    const int omy = (pb + (x << 7) + ym) << 3;

    // smem indices
    const int partner = (r == 0) ? (128 + y) : y;
    const int iyp = (r << 7) + yp;
    const int iym = (r << 7) + ym;

    // staging entries: mine (produce) + the one I consume
    float* my_ent = g_stage[(cta << 8) + (r << 7) + y];
    const float* cs_ent;
    {
        int nslab = (r == 0) ? ((s + 63) & 63) : ((s + 1) & 63);
        int nrow  = (r == 0) ? 1 : 0;
        cs_ent = g_stage[((((pp << 6) | nslab)) << 8) + (nrow << 7) + y];
    }
    unsigned* my_seq = reinterpret_cast<unsigned*>(my_ent + 16);
    const unsigned* cs_seq = reinterpret_cast<const unsigned*>(cs_ent + 16);

    // base: own seq (only this thread writes it -> race-free). All entries
    // advance by exactly T per run -> equal at entry. Wrap-safe unsigned diff.
    const unsigned base = ld_acquire_gpu(my_seq);

    // ---- persistent register state ----
    float xn[8], x0[8], pv[8], q0[8], q1[8], q2[8], xb[8], lam[8], lmx[8], lmy[8];
    float q0m[8], q1m[8];
    LOADP(xn,  xin,   o);
    LOADP(lam, lamin, o);
    LOADP(lmx, lamin, omx);
    LOADP(lmy, lamin, omy);
#pragma unroll
    for (int t = 0; t < 8; t++) {
        x0[t] = xn[t]; pv[t] = xn[t]; xb[t] = xn[t];
        q0[t] = 0.0f;  q1[t] = 0.0f;  q2[t] = 0.0f;
        q0m[t] = 0.0f; q1m[t] = 0.0f;
    }

    // init publish: xbar^0 -> staging buf0 (seq base+1) + smem buf0
    stcg_v4(my_ent + 0, xb[0], xb[1], xb[2], xb[3]);
    stcg_v4(my_ent + 4, xb[4], xb[5], xb[6], xb[7]);
    st_release_gpu_u32(my_seq, base + 1u);
#pragma unroll
    for (int t = 0; t < 8; t++) sm_xb[0][tid][t] = xb[t];
    __syncthreads();

    // ---- main loop ----
    for (int it = 0; it < T; ++it) {
        const int cur = it & 1;

        // intra-CTA halos (ready since last barrier)
        float prt[8], bpy[8], bmy[8];
        LOADS(prt, &sm_xb[cur][partner][0]);
        LOADS(bpy, &sm_xb[cur][iyp][0]);
        LOADS(bmy, &sm_xb[cur][iym][0]);

        // ---- pre-poll compute: everything not needing the remote pencil ----
        float q2n[8], pnv[8], q1n[8], q1mn[8], qx[8];
#pragma unroll
        for (int t = 0; t < 8; t++) {
            float v2 = q2[t] + sig * (xb[(t + 1) & 7] - xb[t]);
            q2n[t] = fminf(fmaxf(v2, -lam[t]), lam[t]);
            pnv[t] = (pv[t] + sig * (xb[t] - xn[t])) * i1s;
            float v1  = q1[t] + sig * (bpy[t] - xb[t]);
            q1n[t] = fminf(fmaxf(v1, -lam[t]), lam[t]);
            float v1m = q1m[t] + sig * (xb[t] - bmy[t]);
            q1mn[t] = fminf(fmaxf(v1m, -lmy[t]), lmy[t]);
        }
        if (r == 0) {
            // bpx = partner (smem): own x-dual is halo-independent
#pragma unroll
            for (int t = 0; t < 8; t++) {
                float v0 = q0[t] + sig * (prt[t] - xb[t]);
                qx[t] = fminf(fmaxf(v0, -lam[t]), lam[t]);      // q0n
            }
        } else {
            // bmx = partner (smem): minus-neighbor x-dual is halo-independent
#pragma unroll
            for (int t = 0; t < 8; t++) {
                float v0m = q0m[t] + sig * (xb[t] - prt[t]);
                qx[t] = fminf(fmaxf(v0m, -lmx[t]), lmx[t]);     // q0mn
            }
        }

        // ---- poll: seq + payload in one L2 line, payload rides the poll ----
        float rem[8];
        {
            const float* pay = cs_ent + (cur << 3);   // buf it&1
            const unsigned need = (unsigned)(it + 1);
            unsigned sv; float4 u, v;
            do {
                sv = ld_acquire_gpu(cs_seq);          // acquire FIRST
                u  = ldcg_v4(pay);                    // ordered after acquire
                v  = ldcg_v4(pay + 4);
            } while (sv - base < need);
            rem[0]=u.x; rem[1]=u.y; rem[2]=u.z; rem[3]=u.w;
            rem[4]=v.x; rem[5]=v.y; rem[6]=v.z; rem[7]=v.w;
        }

        // ---- post-poll: remaining x-dual, divergence, update ----
#pragma unroll
        for (int t = 0; t < 8; t++) {
            float q0n, q0mn;
            if (r == 0) {
                q0n  = qx[t];
                float v0m = q0m[t] + sig * (xb[t] - rem[t]);
                q0mn = fminf(fmaxf(v0m, -lmx[t]), lmx[t]);
            } else {
                q0mn = qx[t];
                float v0 = q0[t] + sig * (rem[t] - xb[t]);
                q0n  = fminf(fmaxf(v0, -lam[t]), lam[t]);
            }
            float dv = (q0mn - q0n) + (q1mn[t] - q1n[t])
                     + (q2n[(t + 7) & 7] - q2n[t]);

            float x1  = x0[t] - tauv * (pnv[t] + dv);
            float xbn = x1 + th * (x1 - x0[t]);

            x0[t] = x1; pv[t] = pnv[t];
            q0[t] = q0n; q1[t] = q1n[t]; q0m[t] = q0mn; q1m[t] = q1mn[t];
            q2[t] = q2n[t];
            xb[t] = xbn;
        }

        if (it != T - 1) {
            // publish to remote consumer FIRST (shortest chain), then smem
            float* pay = my_ent + (((it + 1) & 1) << 3);
            stcg_v4(pay + 0, xb[0], xb[1], xb[2], xb[3]);
            stcg_v4(pay + 4, xb[4], xb[5], xb[6], xb[7]);
            st_release_gpu_u32(my_seq, base + (unsigned)(it + 2));
#pragma unroll
            for (int t = 0; t < 8; t++) sm_xb[cur ^ 1][tid][t] = xb[t];
            __syncthreads();
        }
    }

    // ---- output ----
    STOREP(out, o, x0);
}

extern "C" void kernel_launch(void* const* d_in, const int* in_sizes, int n_in,
                              void* d_out, int out_size) {
    const float* x    = (const float*)d_in[0];
    const float* lam  = (const float*)d_in[1];
    const float* tau  = (const float*)d_in[2];
    const float* sigm = (const float*)d_in[3];
    const float* thet = (const float*)d_in[4];
    const int*   Tp   = (const int*)d_in[5];
    float* out = (float*)d_out;
    pdhg_persist_kernel<<<NCTA, NTHR>>>(x, lam, tau, sigm, thet, Tp, out);
}

// round 15
// speedup vs baseline: 1.3679x; 1.3679x over previous
#include <cuda_runtime.h>
#include <math.h>

// PDHG / Chambolle-Pock TV denoising, persistent kernel, SLAB decomposition.
// P=2, C=1, NX=128, NY=128, NT=8; T=128 iterations.
// CTA = slab of 2 x-rows x full 128 y (256 threads, 1 pencil/thread).
// y-halo + partner-row: intra-CTA via double-buffered SMEM.
// x-halo: dense g_xbar publish + PER-WARP flags (1:1 warp pairing with the
// neighbor CTA). Inter-CTA chain = warp publish -> syncwarp -> lane0 release;
// no __syncthreads on the critical path. Remote payload load is issued at
// discovery and consumed only after ~300cyc of halo-independent compute.

#define NXD 128
#define NYD 128
#define NTD 8
#define NPB 2
#define NPIX (NPB * NXD * NYD * NTD)   // 262144
#define NSLAB 64
#define NCTA (NSLAB * NPB)              // 128
#define NTHR 256
#define NWARP 8

__device__ __align__(256) float g_xbar[2][NPIX];
// one flag per (cta, warp), each on its own 128B line
__device__ __align__(128) unsigned g_wflags[NCTA * NWARP * 32];

// ---- memory-model primitives ----
__device__ __forceinline__ void st_release_gpu(unsigned* p, unsigned v) {
    asm volatile("st.release.gpu.global.u32 [%0], %1;" :: "l"(p), "r"(v) : "memory");
}
__device__ __forceinline__ unsigned ld_acquire_gpu(const unsigned* p) {
    unsigned v;
    asm volatile("ld.acquire.gpu.global.u32 %0, [%1];" : "=r"(v) : "l"(p) : "memory");
    return v;
}

#define LOADP_CG(dst, ptr, off) do { \
    float4 a_ = __ldcg(reinterpret_cast<const float4*>((ptr) + (off))); \
    float4 b_ = __ldcg(reinterpret_cast<const float4*>((ptr) + (off) + 4)); \
    dst[0]=a_.x; dst[1]=a_.y; dst[2]=a_.z; dst[3]=a_.w; \
    dst[4]=b_.x; dst[5]=b_.y; dst[6]=b_.z; dst[7]=b_.w; } while(0)

#define LOADP(dst, ptr, off) do { \
    float4 a_ = *reinterpret_cast<const float4*>((ptr) + (off)); \
    float4 b_ = *reinterpret_cast<const float4*>((ptr) + (off) + 4); \
    dst[0]=a_.x; dst[1]=a_.y; dst[2]=a_.z; dst[3]=a_.w; \
    dst[4]=b_.x; dst[5]=b_.y; dst[6]=b_.z; dst[7]=b_.w; } while(0)

#define STOREP_CG(ptr, off, src) do { \
    __stcg(reinterpret_cast<float4*>((ptr) + (off)),     make_float4(src[0],src[1],src[2],src[3])); \
    __stcg(reinterpret_cast<float4*>((ptr) + (off) + 4), make_float4(src[4],src[5],src[6],src[7])); } while(0)

#define STOREP(ptr, off, src) do { \
    *reinterpret_cast<float4*>((ptr) + (off))     = make_float4(src[0],src[1],src[2],src[3]); \
    *reinterpret_cast<float4*>((ptr) + (off) + 4) = make_float4(src[4],src[5],src[6],src[7]); } while(0)

#define LOADS(dst, smemrow) do { \
    float4 a_ = *reinterpret_cast<const float4*>(smemrow); \
    float4 b_ = *reinterpret_cast<const float4*>((smemrow) + 4); \
    dst[0]=a_.x; dst[1]=a_.y; dst[2]=a_.z; dst[3]=a_.w; \
    dst[4]=b_.x; dst[5]=b_.y; dst[6]=b_.z; dst[7]=b_.w; } while(0)

extern "C" __global__ void __launch_bounds__(NTHR, 1)
pdhg_persist_kernel(const float* __restrict__ xin,
                    const float* __restrict__ lamin,
                    const float* __restrict__ taup,
                    const float* __restrict__ sigp,
                    const float* __restrict__ thp,
                    const int*   __restrict__ Tp,
                    float* __restrict__ out)
{
    __shared__ float sm_xb[2][NTHR][NTD];   // 16 KB, double-buffered xbar

    // ---- scalars ----
    const float L    = sqrtf(13.0f);
    const float sig  = (1.0f / (1.0f + expf(-sigp[0]))) / L;
    const float tauv = (1.0f / (1.0f + expf(-taup[0]))) / L;
    const float th   = 1.0f / (1.0f + expf(-thp[0]));
    const float i1s  = 1.0f / (1.0f + sig);

    int T = Tp[0];
    if (T < 1 || T > 65536) {
        float tf = __int_as_float(T);
        T = (int)tf;
        if (T < 1 || T > 65536) T = 128;
    }

    // ---- mapping ----
    const int cta = blockIdx.x;           // 0..127
    const int pp  = cta >> 6;             // batch
    const int s   = cta & 63;             // slab (rows 2s, 2s+1)
    const int tid = threadIdx.x;
    const int w   = tid >> 5;             // warp 0..7
    const int r   = tid >> 7;             // 0 or 1 (warps 0-3 / 4-7)
    const int y   = tid & 127;
    const int x   = (s << 1) + r;
    const int yp  = (y + 1) & 127, ym = (y - 1) & 127;

    const int pb = pp << 14;
    const int o  = (pb + (x << 7) + y) << 3;
    const int omx = (pb + (((x - 1) & 127) << 7) + y) << 3;
    const int omy = (pb + (x << 7) + ym) << 3;

    // the single remote pencil this thread needs
    const int xr = (r == 0) ? ((x - 1) & 127) : ((x + 1) & 127);
    const int orem = (pb + (xr << 7) + y) << 3;

    // smem indices
    const int partner = (r == 0) ? (128 + y) : y;
    const int iyp = (r << 7) + yp;
    const int iym = (r << 7) + ym;

    // ---- per-warp flags: my flag + partner warp's flag in neighbor CTA ----
    // Partner of warp w: neighbor slab, other row, same y-block.
    unsigned* my_flag = &g_wflags[(cta * NWARP + w) * 32];
    const unsigned* nbr_flag;
    {
        int nslab = (r == 0) ? ((s + 63) & 63) : ((s + 1) & 63);
        int ncta  = (pp << 6) | nslab;
        int nwarp = (r == 0) ? (4 + (w & 3)) : (w & 3);
        nbr_flag = &g_wflags[(ncta * NWARP + nwarp) * 32];
    }
    // base: own flag; only this warp's lane0 writes it -> race-free read.
    // All flags advance by exactly T per run -> equal at entry. Wrap-safe diff.
    unsigned base = 0;
    if ((tid & 31) == 0) base = ld_acquire_gpu(my_flag);
    base = __shfl_sync(0xffffffffu, base, 0);

    // ---- persistent register state ----
    float xn[8], x0[8], pv[8], q0[8], q1[8], q2[8], xb[8], lam[8], lmx[8], lmy[8];
    float q0m[8], q1m[8];
    LOADP(xn,  xin,   o);
    LOADP(lam, lamin, o);
    LOADP(lmx, lamin, omx);
    LOADP(lmy, lamin, omy);
#pragma unroll
    for (int t = 0; t < 8; t++) {
        x0[t] = xn[t]; pv[t] = xn[t]; xb[t] = xn[t];
        q0[t] = 0.0f;  q1[t] = 0.0f;  q2[t] = 0.0f;
        q0m[t] = 0.0f; q1m[t] = 0.0f;
    }

    // init publish: xbar^0 -> g_xbar buf0 (warp-release flag base+1) + smem buf0
    STOREP_CG(g_xbar[0], o, xb);
    __syncwarp();
    if ((tid & 31) == 0) st_release_gpu(my_flag, base + 1u);
#pragma unroll
    for (int t = 0; t < 8; t++) sm_xb[0][tid][t] = xb[t];
    __syncthreads();

    // ---- main loop ----
    for (int it = 0; it < T; ++it) {
        const int cur = it & 1;

        // 1. discovery: lane0 polls ONE partner-warp flag (benign traffic).
        //    flag >= it+1 also proves write-safety of buf cur^1 below: the
        //    partner finished iteration it-1, the last consumer of that buf.
        if ((tid & 31) == 0) {
            const unsigned need = (unsigned)(it + 1);
            while (ld_acquire_gpu(nbr_flag) - base < need) { }
        }
        __syncwarp();

        // 2. remote pencil load issued NOW, consumed after pre-compute.
        float rem[8];
        LOADP_CG(rem, g_xbar[cur], orem);

        // 3. smem halos + all halo-independent compute (hides the LDG latency)
        float prt[8], bpy[8], bmy[8];
        LOADS(prt, &sm_xb[cur][partner][0]);
        LOADS(bpy, &sm_xb[cur][iyp][0]);
        LOADS(bmy, &sm_xb[cur][iym][0]);

        float q2n[8], pnv[8], q1n[8], q1mn[8], qx[8];
#pragma unroll
        for (int t = 0; t < 8; t++) {
            float v2 = q2[t] + sig * (xb[(t + 1) & 7] - xb[t]);
            q2n[t] = fminf(fmaxf(v2, -lam[t]), lam[t]);
            pnv[t] = (pv[t] + sig * (xb[t] - xn[t])) * i1s;
            float v1  = q1[t] + sig * (bpy[t] - xb[t]);
            q1n[t] = fminf(fmaxf(v1, -lam[t]), lam[t]);
            float v1m = q1m[t] + sig * (xb[t] - bmy[t]);
            q1mn[t] = fminf(fmaxf(v1m, -lmy[t]), lmy[t]);
        }
        if (r == 0) {
            // bpx = partner (smem): own x-dual is halo-independent
#pragma unroll
            for (int t = 0; t < 8; t++) {
                float v0 = q0[t] + sig * (prt[t] - xb[t]);
                qx[t] = fminf(fmaxf(v0, -lam[t]), lam[t]);      // q0n
            }
        } else {
            // bmx = partner (smem): minus-neighbor x-dual is halo-independent
#pragma unroll
            for (int t = 0; t < 8; t++) {
                float v0m = q0m[t] + sig * (xb[t] - prt[t]);
                qx[t] = fminf(fmaxf(v0m, -lmx[t]), lmx[t]);     // q0mn
            }
        }

        // 4. post-compute: remaining x-dual, divergence, update
#pragma unroll
        for (int t = 0; t < 8; t++) {
            float q0n, q0mn;
            if (r == 0) {
                q0n  = qx[t];
                float v0m = q0m[t] + sig * (xb[t] - rem[t]);
                q0mn = fminf(fmaxf(v0m, -lmx[t]), lmx[t]);
            } else {
                q0mn = qx[t];
                float v0 = q0[t] + sig * (rem[t] - xb[t]);
                q0n  = fminf(fmaxf(v0, -lam[t]), lam[t]);
            }
            float dv = (q0mn - q0n) + (q1mn[t] - q1n[t])
                     + (q2n[(t + 7) & 7] - q2n[t]);

            float x1  = x0[t] - tauv * (pnv[t] + dv);
            float xbn = x1 + th * (x1 - x0[t]);

            x0[t] = x1; pv[t] = pnv[t];
            q0[t] = q0n; q1[t] = q1n[t]; q0m[t] = q0mn; q1m[t] = q1mn[t];
            q2[t] = q2n[t];
            xb[t] = xbn;
        }

        if (it != T - 1) {
            // 5. publish global payload + warp flag FIRST (shortest remote
            //    chain: no CTA barrier involved), then smem + CTA barrier.
            STOREP_CG(g_xbar[cur ^ 1], o, xb);
            __syncwarp();
            if ((tid & 31) == 0)
                st_release_gpu(my_flag, base + (unsigned)(it + 2));
#pragma unroll
            for (int t = 0; t < 8; t++) sm_xb[cur ^ 1][tid][t] = xb[t];
            __syncthreads();
        }
    }

    // ---- output ----
    STOREP(out, o, x0);
}

extern "C" void kernel_launch(void* const* d_in, const int* in_sizes, int n_in,
                              void* d_out, int out_size) {
    const float* x    = (const float*)d_in[0];
    const float* lam  = (const float*)d_in[1];
    const float* tau  = (const float*)d_in[2];
    const float* sigm = (const float*)d_in[3];
    const float* thet = (const float*)d_in[4];
    const int*   Tp   = (const int*)d_in[5];
    float* out = (float*)d_out;
    pdhg_persist_kernel<<<NCTA, NTHR>>>(x, lam, tau, sigm, thet, Tp, out);
}